// round 9
// baseline (speedup 1.0000x reference)
#include <cuda_runtime.h>

// UnarySqrt recurrence, unipolar, jk_trace=True.
// On exact {0.0f, 1.0f} IEEE patterns (0x00000000 / 0x3F800000):
//   out    = trace | x     ( == (1-trace)*x + trace )
//   trace' = x & ~trace    ( == out * (1-trace) )
// Bit-exact vs the float reference (rel_err=0.0 since R3).
//
// R9: software-pipelined chunks with DEFAULT cache policy (the R5 structure
// was only ever tested with __ldcs/__stcs hints, which we've since shown cost
// ~5us of replay-to-replay L2 retention on the bench). Prefetch the next
// CH=2-step chunk of both column streams before computing+storing the current
// one: sustained 8 loads in flight per thread, stores spread uniformly (no
// terminal 8-store burst colliding with the next graph replay's load front).
// Geometry: 128 thr x 1024 CTAs (R8's balanced {6,7} CTAs/SM, one wave).

#define T_STEPS 64
#define CH 2

__device__ __forceinline__ void step_chunk(uint4 x[CH], uint4& tr)
{
    #pragma unroll
    for (int k = 0; k < CH; ++k) {
        uint4 o;
        o.x = x[k].x | tr.x;   o.y = x[k].y | tr.y;
        o.z = x[k].z | tr.z;   o.w = x[k].w | tr.w;
        tr.x = x[k].x & ~tr.x; tr.y = x[k].y & ~tr.y;
        tr.z = x[k].z & ~tr.z; tr.w = x[k].w & ~tr.w;
        x[k] = o;              // x[k] now holds out
    }
}

__global__ __launch_bounds__(128)
void unary_sqrt_kernel(const uint4* __restrict__ bits,
                       const uint4* __restrict__ trace0,
                       uint4* __restrict__ out,
                       int nvec, int half)
{
    int i = blockIdx.x * blockDim.x + threadIdx.x;
    if (i >= half) return;
    int j = i + half;

    uint4 ta = trace0[i];
    uint4 tb = trace0[j];

    uint4 xa[CH], xb[CH];   // current chunk
    uint4 ya[CH], yb[CH];   // prefetched next chunk

    // prologue: load chunk 0 (default policy)
    #pragma unroll
    for (int k = 0; k < CH; ++k) {
        const size_t base = (size_t)k * nvec;
        xa[k] = bits[base + i];
        xb[k] = bits[base + j];
    }

    #pragma unroll
    for (int tbase = 0; tbase < T_STEPS; tbase += CH) {
        // prefetch next chunk (address-independent of current compute)
        if (tbase + CH < T_STEPS) {
            #pragma unroll
            for (int k = 0; k < CH; ++k) {
                const size_t base = (size_t)(tbase + CH + k) * nvec;
                ya[k] = bits[base + i];
                yb[k] = bits[base + j];
            }
        }

        // compute current chunk
        step_chunk(xa, ta);
        step_chunk(xb, tb);

        // store current chunk (default policy, spread through the kernel)
        #pragma unroll
        for (int k = 0; k < CH; ++k) {
            const size_t base = (size_t)(tbase + k) * nvec;
            out[base + i] = xa[k];
            out[base + j] = xb[k];
        }

        // rotate
        #pragma unroll
        for (int k = 0; k < CH; ++k) {
            xa[k] = ya[k];
            xb[k] = yb[k];
        }
    }
}

extern "C" void kernel_launch(void* const* d_in, const int* in_sizes, int n_in,
                              void* d_out, int out_size)
{
    // metadata order: input [T, N] float32, trace0 [N] float32
    const uint4* bits   = (const uint4*)d_in[0];
    const uint4* trace0 = (const uint4*)d_in[1];
    uint4*       out    = (uint4*)d_out;

    int N    = in_sizes[1];   // 1048576
    int nvec = N / 4;         // 262144 uint4 vectors
    int half = nvec / 2;      // 131072

    int threads = 128;
    int blocks  = (half + threads - 1) / threads;  // 1024 -> {6,7} CTAs/SM, 1 wave
    unary_sqrt_kernel<<<blocks, threads>>>(bits, trace0, out, nvec, half);
}

// round 10
// speedup vs baseline: 1.0231x; 1.0231x over previous
#include <cuda_runtime.h>

// UnarySqrt recurrence, unipolar, jk_trace=True.
// On exact {0.0f, 1.0f} IEEE patterns (0x00000000 / 0x3F800000):
//   out    = trace | x     ( == (1-trace)*x + trace )
//   trace' = x & ~trace    ( == out * (1-trace) )
// Bit-exact vs the float reference (rel_err=0.0 since R3).
//
// R10: R8 (time-tiled bursts, 2 column streams/thread, default cache policy,
// 128thr x 1024 CTAs) with burst depth raised 8 -> 12 loads: CH=6 chunks
// (10 of them) + one CH=4 tail. MLP has been the monotone driver of DRAM%
// (2->68%, 4->73%, 8->77%). __launch_bounds__(128,7) pins 7 CTAs/SM so the
// grid stays a single balanced wave ({6,7} CTAs/SM).

#define T_STEPS 64

template<int C>
__device__ __forceinline__ void do_chunk(const uint4* __restrict__ bits,
                                         uint4* __restrict__ out,
                                         int nvec, int i, int j, int tbase,
                                         uint4& ta, uint4& tb)
{
    uint4 xa[C], xb[C];

    // burst: 2*C address-independent 16B loads (default policy)
    #pragma unroll
    for (int k = 0; k < C; ++k) {
        const size_t base = (size_t)(tbase + k) * nvec;
        xa[k] = bits[base + i];
        xb[k] = bits[base + j];
    }

    // recurrence (in-place: x[k] becomes out[k])
    #pragma unroll
    for (int k = 0; k < C; ++k) {
        uint4 oa, ob;
        oa.x = xa[k].x | ta.x;  oa.y = xa[k].y | ta.y;
        oa.z = xa[k].z | ta.z;  oa.w = xa[k].w | ta.w;
        ob.x = xb[k].x | tb.x;  ob.y = xb[k].y | tb.y;
        ob.z = xb[k].z | tb.z;  ob.w = xb[k].w | tb.w;

        ta.x = xa[k].x & ~ta.x;  ta.y = xa[k].y & ~ta.y;
        ta.z = xa[k].z & ~ta.z;  ta.w = xa[k].w & ~ta.w;
        tb.x = xb[k].x & ~tb.x;  tb.y = xb[k].y & ~tb.y;
        tb.z = xb[k].z & ~tb.z;  tb.w = xb[k].w & ~tb.w;

        xa[k] = oa;  xb[k] = ob;
    }

    // burst: 2*C back-to-back 16B stores (default policy)
    #pragma unroll
    for (int k = 0; k < C; ++k) {
        const size_t base = (size_t)(tbase + k) * nvec;
        out[base + i] = xa[k];
        out[base + j] = xb[k];
    }
}

__global__ __launch_bounds__(128, 7)
void unary_sqrt_kernel(const uint4* __restrict__ bits,
                       const uint4* __restrict__ trace0,
                       uint4* __restrict__ out,
                       int nvec, int half)
{
    int i = blockIdx.x * blockDim.x + threadIdx.x;
    if (i >= half) return;
    int j = i + half;

    uint4 ta = trace0[i];
    uint4 tb = trace0[j];

    // 10 chunks of 6 t-steps (keep outer loop rolled for I$)
    #pragma unroll 1
    for (int tbase = 0; tbase < 60; tbase += 6)
        do_chunk<6>(bits, out, nvec, i, j, tbase, ta, tb);

    // tail: 4 t-steps
    do_chunk<4>(bits, out, nvec, i, j, 60, ta, tb);
}

extern "C" void kernel_launch(void* const* d_in, const int* in_sizes, int n_in,
                              void* d_out, int out_size)
{
    // metadata order: input [T, N] float32, trace0 [N] float32
    const uint4* bits   = (const uint4*)d_in[0];
    const uint4* trace0 = (const uint4*)d_in[1];
    uint4*       out    = (uint4*)d_out;

    int N    = in_sizes[1];   // 1048576
    int nvec = N / 4;         // 262144 uint4 vectors
    int half = nvec / 2;      // 131072

    int threads = 128;
    int blocks  = (half + threads - 1) / threads;  // 1024 -> {6,7} CTAs/SM, 1 wave
    unary_sqrt_kernel<<<blocks, threads>>>(bits, trace0, out, nvec, half);
}